// round 1
// baseline (speedup 1.0000x reference)
#include <cuda_runtime.h>
#include <cstdint>

// Problem constants (fixed by the dataset: E=8, R=64, B=4, S=4096, D=2048)
#define E_N   8
#define RNK   64
#define DIM   2048
#define NTOK  16384
#define TM    128      // tokens per tile
#define KC    64       // k-chunk for stage 1
#define NC    128      // n-chunk for stage 2
#define NTHR  256

// ---------------- device scratch (no allocation allowed) ----------------
__device__ int g_count[E_N];
__device__ int g_offset[E_N];
__device__ int g_fill[E_N];
__device__ int g_tokens[NTOK];

// ---------------- packed fp32x2 helpers ----------------
__device__ __forceinline__ void fma2(unsigned long long &c,
                                     unsigned long long a,
                                     unsigned long long b) {
    asm("fma.rn.f32x2 %0, %1, %2, %0;" : "+l"(c) : "l"(a), "l"(b));
}
__device__ __forceinline__ unsigned long long pack2(float x) {
    unsigned long long r;
    asm("mov.b64 %0, {%1, %1};" : "=l"(r) : "f"(x));
    return r;
}
union F4U {
    float4 f;
    unsigned long long u[2];
    float s[4];
};
union U2F {
    unsigned long long u;
    float f[2];
};

// ---------------- sort-by-expert kernels ----------------
__global__ void k_zero() {
    int i = threadIdx.x;
    if (i < E_N) g_count[i] = 0;
}

__global__ void k_hist(const int* __restrict__ idx) {
    int t = blockIdx.x * blockDim.x + threadIdx.x;
    if (t < NTOK) atomicAdd(&g_count[idx[t]], 1);
}

__global__ void k_scan() {
    if (threadIdx.x == 0 && blockIdx.x == 0) {
        int acc = 0;
        for (int e = 0; e < E_N; ++e) {
            g_offset[e] = acc;
            g_fill[e]   = acc;
            acc += g_count[e];
        }
    }
}

__global__ void k_scatter(const int* __restrict__ idx) {
    int t = blockIdx.x * blockDim.x + threadIdx.x;
    if (t < NTOK) {
        int p = atomicAdd(&g_fill[idx[t]], 1);
        g_tokens[p] = t;
    }
}

// ---------------- fused per-expert tile GEMM ----------------
//
// SMEM layout (floats):
//   [0     .. 8192)  : Xs  (64 k-rows x 128 m, XOR-swizzled granules)  / reused as Bs in stage 2
//   [8192  .. 12288) : As  (64 k-rows x 64 r, XOR-swizzled)
//   [12288 .. 20480) : Hs  (64 r-rows x 128 m, XOR-swizzled)
//   [20480 .. 20608) : tok (128 ints)
// total = 20608 floats = 82432 bytes (dynamic)
#define SM_XS 0
#define SM_AS 8192
#define SM_HS 12288
#define SM_TOK 20480
#define SMEM_BYTES (20608 * 4)

__global__ void __launch_bounds__(NTHR, 2)
k_main(const float* __restrict__ x,
       const float* __restrict__ Aw,
       const float* __restrict__ Bw,
       float* __restrict__ out) {
    const int e = blockIdx.y;
    const int cnt = g_count[e];
    const int mstart = blockIdx.x * TM;
    if (mstart >= cnt) return;
    const int base = g_offset[e];

    extern __shared__ float sm[];
    float* Xs = sm + SM_XS;      // stage2: Bs
    float* As = sm + SM_AS;
    float* Hs = sm + SM_HS;
    int*   tok = (int*)(sm + SM_TOK);

    const int tid = threadIdx.x;
    const int tx = tid & 15;     // r-group (stage1) / n-group (stage2)
    const int ty = tid >> 4;     // m-group

    if (tid < TM) {
        int i = mstart + tid;
        tok[tid] = (i < cnt) ? g_tokens[base + i] : -1;
    }
    __syncthreads();

    // ============ stage 1: H[128m][64r] = X[128m][2048k] * A^T ============
    // acc1[p][j]: m-pair p (m = ty*8 + 2p + lane), r = tx*4 + j
    unsigned long long acc1[4][4];
#pragma unroll
    for (int p = 0; p < 4; ++p)
#pragma unroll
        for (int j = 0; j < 4; ++j) acc1[p][j] = 0ull;

    const float* Arow = Aw + (size_t)e * RNK * DIM;

    for (int k0 = 0; k0 < DIM; k0 += KC) {
        __syncthreads();
        // fill Xs: coalesced 256B per token row, transpose to k-major w/ swizzle
        {
            const int l = tid & 15;       // k-float4 index
            const int mr = tid >> 4;      // row group
#pragma unroll
            for (int it = 0; it < 8; ++it) {
                int m = it * 16 + mr;
                int t = tok[m];
                float4 v = make_float4(0.f, 0.f, 0.f, 0.f);
                if (t >= 0) v = *(const float4*)(x + (size_t)t * DIM + k0 + l * 4);
                F4U u; u.f = v;
#pragma unroll
                for (int j = 0; j < 4; ++j) {
                    int k = l * 4 + j;
                    Xs[k * 128 + 4 * (((m >> 2) ^ (k & 31))) + (m & 3)] = u.s[j];
                }
            }
        }
        // fill As: coalesced along k, transpose to k-major w/ swizzle
        {
#pragma unroll
            for (int it = 0; it < 4; ++it) {
                int idx = it * 256 + tid;
                int r = idx >> 4;
                int l = idx & 15;
                F4U u;
                u.f = *(const float4*)(Arow + (size_t)r * DIM + k0 + l * 4);
#pragma unroll
                for (int j = 0; j < 4; ++j) {
                    int k = l * 4 + j;
                    As[k * 64 + 4 * (((r >> 2) ^ (k & 15))) + (r & 3)] = u.s[j];
                }
            }
        }
        __syncthreads();

#pragma unroll 4
        for (int kk = 0; kk < KC; ++kk) {
            const int s32 = kk & 31;
            F4U X0, X1, Av;
            X0.f = *(const float4*)(Xs + kk * 128 + 4 * ((2 * ty) ^ s32));
            X1.f = *(const float4*)(Xs + kk * 128 + 4 * ((2 * ty + 1) ^ s32));
            Av.f = *(const float4*)(As + kk * 64 + 4 * (tx ^ (kk & 15)));
            unsigned long long xp[4] = {X0.u[0], X0.u[1], X1.u[0], X1.u[1]};
#pragma unroll
            for (int j = 0; j < 4; ++j) {
                unsigned long long aj = pack2(Av.s[j]);
#pragma unroll
                for (int p = 0; p < 4; ++p) fma2(acc1[p][j], xp[p], aj);
            }
        }
    }

    // write H -> SMEM (r-major, m-granule swizzled)
#pragma unroll
    for (int p = 0; p < 4; ++p)
#pragma unroll
        for (int j = 0; j < 4; ++j) {
            U2F v; v.u = acc1[p][j];
            int r = tx * 4 + j;
#pragma unroll
            for (int b = 0; b < 2; ++b) {
                int m = ty * 8 + p * 2 + b;
                Hs[r * 128 + 4 * (((m >> 2) ^ (r & 31))) + (m & 3)] = v.f[b];
            }
        }

    // ============ stage 2: O[128m][2048n] = H[128m][64r] * B_e^T ============
    const float* Brow = Bw + (size_t)e * DIM * RNK;
    float* Bs = Xs;  // reuse

    for (int nc = 0; nc < DIM; nc += NC) {
        __syncthreads();  // prior readers of Bs / (first iter) Xs-As done
        // fill Bs: B[e][n][r] -> Bs[r][n] (r-major, n-granule swizzled)
#pragma unroll
        for (int it = 0; it < 8; ++it) {
            int idx = it * 256 + tid;
            int n = idx >> 4;
            int l = idx & 15;
            F4U u;
            u.f = *(const float4*)(Brow + (size_t)(nc + n) * RNK + l * 4);
#pragma unroll
            for (int j = 0; j < 4; ++j) {
                int r = l * 4 + j;
                Bs[r * 128 + 4 * (((n >> 2) ^ (r & 31))) + (n & 3)] = u.s[j];
            }
        }
        __syncthreads();

        unsigned long long acc2[4][8];
#pragma unroll
        for (int p = 0; p < 4; ++p)
#pragma unroll
            for (int j = 0; j < 8; ++j) acc2[p][j] = 0ull;

#pragma unroll 4
        for (int rr = 0; rr < RNK; ++rr) {
            const int s32 = rr & 31;
            F4U H0, H1, B0, B1;
            H0.f = *(const float4*)(Hs + rr * 128 + 4 * ((2 * ty) ^ s32));
            H1.f = *(const float4*)(Hs + rr * 128 + 4 * ((2 * ty + 1) ^ s32));
            B0.f = *(const float4*)(Bs + rr * 128 + 4 * ((2 * tx) ^ s32));
            B1.f = *(const float4*)(Bs + rr * 128 + 4 * ((2 * tx + 1) ^ s32));
            unsigned long long hp[4] = {H0.u[0], H0.u[1], H1.u[0], H1.u[1]};
            float bsc[8] = {B0.s[0], B0.s[1], B0.s[2], B0.s[3],
                            B1.s[0], B1.s[1], B1.s[2], B1.s[3]};
#pragma unroll
            for (int j = 0; j < 8; ++j) {
                unsigned long long bj = pack2(bsc[j]);
#pragma unroll
                for (int p = 0; p < 4; ++p) fma2(acc2[p][j], hp[p], bj);
            }
        }

        // epilogue: coalesced float4 stores (SCALE = 1.0)
#pragma unroll
        for (int p = 0; p < 4; ++p)
#pragma unroll
            for (int b = 0; b < 2; ++b) {
                int m = ty * 8 + p * 2 + b;
                int t = tok[m];
                if (t >= 0) {
                    float o[8];
#pragma unroll
                    for (int j = 0; j < 8; ++j) {
                        U2F c; c.u = acc2[p][j];
                        o[j] = c.f[b];
                    }
                    float4* dst = (float4*)(out + (size_t)t * DIM + nc + tx * 8);
                    dst[0] = make_float4(o[0], o[1], o[2], o[3]);
                    dst[1] = make_float4(o[4], o[5], o[6], o[7]);
                }
            }
    }
}

// ---------------- launch ----------------
extern "C" void kernel_launch(void* const* d_in, const int* in_sizes, int n_in,
                              void* d_out, int out_size) {
    const float* x   = (const float*)d_in[0];   // [B,S,D] fp32
    const float* Aw  = (const float*)d_in[1];   // [E,R,D] fp32
    const float* Bw  = (const float*)d_in[2];   // [E,D,R] fp32
    const int*   ti  = (const int*)d_in[3];     // [B,S] int32
    float* out = (float*)d_out;
    (void)in_sizes; (void)n_in; (void)out_size;

    // Opt into >48KB dynamic smem (idempotent; executes immediately, not captured)
    static int smem_set = 0;
    if (!smem_set) {
        cudaFuncSetAttribute(k_main, cudaFuncAttributeMaxDynamicSharedMemorySize,
                             SMEM_BYTES);
        smem_set = 1;
    }

    k_zero<<<1, 32>>>();
    k_hist<<<NTOK / 256, 256>>>(ti);
    k_scan<<<1, 1>>>();
    k_scatter<<<NTOK / 256, 256>>>(ti);

    dim3 grid(NTOK / TM, E_N, 1);   // 128 tiles (worst case) x 8 experts, early-exit
    k_main<<<grid, NTHR, SMEM_BYTES>>>(x, Aw, Bw, out);
}

// round 4
// speedup vs baseline: 3.5616x; 3.5616x over previous
#include <cuda_runtime.h>
#include <cuda_bf16.h>
#include <cstdint>

// Problem constants (E=8, R=64, B=4, S=4096, D=2048)
#define E_N   8
#define RNK   64
#define DIM   2048
#define NTOK  16384
#define TM    128
#define NTHR  256

// ---------------- device scratch ----------------
__device__ int g_count[E_N];
__device__ int g_offset[E_N];
__device__ int g_tokens[NTOK];

// ---------------- helpers ----------------
__device__ __forceinline__ uint32_t smem_u32(const void* p) {
    uint32_t a;
    asm("{ .reg .u64 t; cvta.to.shared.u64 t, %1; cvt.u32.u64 %0, t; }" : "=r"(a) : "l"(p));
    return a;
}
__device__ __forceinline__ uint32_t swz(uint32_t o) { return o ^ ((o >> 3) & 0x70); }

// split fp32 pair -> packed bf16 hi-pair + lo-pair
__device__ __forceinline__ void split2(float a, float b, uint32_t& hi, uint32_t& lo) {
    __nv_bfloat16 ha = __float2bfloat16_rn(a), hb = __float2bfloat16_rn(b);
    float ra = a - __bfloat162float(ha), rb = b - __bfloat162float(hb);
    __nv_bfloat16 la = __float2bfloat16_rn(ra), lb = __float2bfloat16_rn(rb);
    hi = ((uint32_t)__bfloat16_as_ushort(hb) << 16) | (uint32_t)__bfloat16_as_ushort(ha);
    lo = ((uint32_t)__bfloat16_as_ushort(lb) << 16) | (uint32_t)__bfloat16_as_ushort(la);
}

__device__ __forceinline__ void ldm_x4(uint32_t a, uint32_t r[4]) {
    asm volatile("ldmatrix.sync.aligned.m8n8.x4.shared.b16 {%0,%1,%2,%3}, [%4];"
                 : "=r"(r[0]), "=r"(r[1]), "=r"(r[2]), "=r"(r[3]) : "r"(a));
}
__device__ __forceinline__ void mma16816(float* c, const uint32_t a[4], const uint32_t* b) {
    asm volatile("mma.sync.aligned.m16n8k16.row.col.f32.bf16.bf16.f32 "
                 "{%0,%1,%2,%3}, {%4,%5,%6,%7}, {%8,%9}, {%0,%1,%2,%3};"
                 : "+f"(c[0]), "+f"(c[1]), "+f"(c[2]), "+f"(c[3])
                 : "r"(a[0]), "r"(a[1]), "r"(a[2]), "r"(a[3]), "r"(b[0]), "r"(b[1]));
}

// ---------------- SMEM layout (bytes) ----------------
// 64    : tok[128]
// 1024  : stage1 buf0 {Xhi 16K, Xlo 16K, Ahi 8K, Alo 8K} = 48K ; buf1 @ 50176
// 99328 : Hhi 16K ; 115712 : Hlo 16K  (end 132096)
// stage2 B reuses 1024..: buf {Bhi 16K, Blo 16K} = 32K; buf0 @1024, buf1 @33792
#define SM_TOK    64
#define SM_XA0    1024
#define XA_STRIDE 49152
#define OFF_XLO   16384
#define OFF_AHI   32768
#define OFF_ALO   40960
#define SM_HHI    99328
#define SM_HLO    115712
#define SMEM_BYTES 132096

// ---------------- sort kernel (single CTA) ----------------
__global__ void __launch_bounds__(1024) k_sort(const int* __restrict__ ti) {
    __shared__ int sc[E_N];
    __shared__ int sb[E_N];
    const int tid = threadIdx.x;
    const int lane = tid & 31;
    if (tid < E_N) sc[tid] = 0;
    __syncthreads();
    for (int t = tid; t < NTOK; t += 1024) {
        int e = ti[t];
        unsigned mask = __match_any_sync(0xffffffffu, e);
        int leader = __ffs(mask) - 1;
        if (lane == leader) atomicAdd(&sc[e], __popc(mask));
    }
    __syncthreads();
    if (tid == 0) {
        int acc = 0;
        for (int e = 0; e < E_N; ++e) {
            g_count[e] = sc[e];
            g_offset[e] = acc;
            sb[e] = acc;
            acc += sc[e];
        }
    }
    __syncthreads();
    for (int t = tid; t < NTOK; t += 1024) {
        int e = ti[t];
        unsigned mask = __match_any_sync(0xffffffffu, e);
        int leader = __ffs(mask) - 1;
        int prior = __popc(mask & ((1u << lane) - 1));
        int base = 0;
        if (lane == leader) base = atomicAdd(&sb[e], __popc(mask));
        base = __shfl_sync(0xffffffffu, base, leader);
        g_tokens[base + prior] = t;
    }
}

// ---------------- main kernel ----------------
__global__ void __launch_bounds__(NTHR, 1)
k_main(const float* __restrict__ x,
       const float* __restrict__ Aw,
       const float* __restrict__ Bw,
       float* __restrict__ out) {
    const int e = blockIdx.y;
    const int cnt = g_count[e];
    const int mstart = blockIdx.x * TM;
    if (mstart >= cnt) return;
    const int base = g_offset[e];

    extern __shared__ char smc[];
    const uint32_t sbu = smem_u32(smc);
    const int tid = threadIdx.x;
    const int wid = tid >> 5;
    const int lane = tid & 31;
    const int m0 = wid * 16;
    const int g = lane >> 2;
    const int tq = lane & 3;
    int* tok = (int*)(smc + SM_TOK);

    if (tid < TM) {
        int i = mstart + tid;
        tok[tid] = (i < cnt) ? g_tokens[base + i] : -1;
    }
    __syncthreads();

    const float* Arow = Aw + (size_t)e * RNK * DIM;
    const float* Brow = Bw + (size_t)e * DIM * RNK;

    // fill-thread mappings
    const int fm = tid & 127, fkh = tid >> 7;            // X: row, k-half
    const int fr = tid >> 2, fq = tid & 3;               // A: row, k-quarter
    const int ftok = tok[fm];
    const float* xsrc = (ftok >= 0) ? (x + (size_t)ftok * DIM + fkh * 32) : x;

    // ldmatrix byte-offset patterns (pre-swizzle)
    // A-operand (16 rows x 16 k-bytes across 4 matrices)
    const uint32_t xrow_off = (uint32_t)(m0 + (lane & 15)) * 128 + (uint32_t)(lane >> 4) * 16;
    // B-operand pair (two adjacent 8-row n-blocks per x4)
    const uint32_t brow4_off = (uint32_t)((lane & 7) + (lane >> 4) * 8) * 128 +
                               (uint32_t)((lane >> 3) & 1) * 16;

    float4 vx[8], va[4];

    // ===== stage 1: H[128,64] = X[128,2048] * A_e^T, 32 k-chunks of 64 =====
    float acc1[8][4];
#pragma unroll
    for (int j = 0; j < 8; ++j)
#pragma unroll
        for (int q = 0; q < 4; ++q) acc1[j][q] = 0.f;

#pragma unroll
    for (int i = 0; i < 8; ++i)
        vx[i] = (ftok >= 0) ? *(const float4*)(xsrc + i * 4) : make_float4(0.f, 0.f, 0.f, 0.f);
#pragma unroll
    for (int i = 0; i < 4; ++i)
        va[i] = *(const float4*)(Arow + (size_t)fr * DIM + fq * 16 + i * 4);

#define STORE_XA(BUF)                                                          \
    do {                                                                       \
        char* bXh = smc + SM_XA0 + (BUF) * XA_STRIDE;                          \
        char* bXl = bXh + OFF_XLO;                                             \
        char* bAh = bXh + OFF_AHI;                                             \
        char* bAl = bXh + OFF_ALO;                                             \
        uint32_t rb = (uint32_t)fm * 128 + (uint32_t)fkh * 64;                 \
        _Pragma("unroll") for (int i = 0; i < 8; ++i) {                        \
            uint32_t h0, l0, h1, l1;                                           \
            split2(vx[i].x, vx[i].y, h0, l0);                                  \
            split2(vx[i].z, vx[i].w, h1, l1);                                  \
            uint32_t off = swz(rb + i * 8);                                    \
            *(uint2*)(bXh + off) = make_uint2(h0, h1);                         \
            *(uint2*)(bXl + off) = make_uint2(l0, l1);                         \
        }                                                                      \
        uint32_t rb2 = (uint32_t)fr * 128 + (uint32_t)fq * 32;                 \
        _Pragma("unroll") for (int i = 0; i < 4; ++i) {                        \
            uint32_t h0, l0, h1, l1;                                           \
            split2(va[i].x, va[i].y, h0, l0);                                  \
            split2(va[i].z, va[i].w, h1, l1);                                  \
            uint32_t off = swz(rb2 + i * 8);                                   \
            *(uint2*)(bAh + off) = make_uint2(h0, h1);                         \
            *(uint2*)(bAl + off) = make_uint2(l0, l1);                         \
        }                                                                      \
    } while (0)

#define LOAD_XA(K0)                                                            \
    do {                                                                       \
        _Pragma("unroll") for (int i = 0; i < 8; ++i) vx[i] =                  \
            (ftok >= 0) ? *(const float4*)(xsrc + (K0) + i * 4)                \
                        : make_float4(0.f, 0.f, 0.f, 0.f);                     \
        _Pragma("unroll") for (int i = 0; i < 4; ++i) va[i] =                  \
            *(const float4*)(Arow + (size_t)fr * DIM + (K0) + fq * 16 + i * 4);\
    } while (0)

    STORE_XA(0);
    __syncthreads();
    LOAD_XA(64);

    for (int c = 0; c < 32; ++c) {
        const uint32_t xb = sbu + SM_XA0 + (uint32_t)(c & 1) * XA_STRIDE;
#pragma unroll
        for (int kk = 0; kk < 4; ++kk) {
            uint32_t xh[4], xl[4];
            uint32_t xoff = swz(xrow_off + kk * 32);
            ldm_x4(xb + xoff, xh);
            ldm_x4(xb + OFF_XLO + xoff, xl);
#pragma unroll
            for (int j = 0; j < 8; j += 2) {
                uint32_t bh[4], bl[4];
                uint32_t aoff = swz(brow4_off + j * 1024 + kk * 32);
                ldm_x4(xb + OFF_AHI + aoff, bh);
                ldm_x4(xb + OFF_ALO + aoff, bl);
                mma16816(acc1[j], xh, bh);
                mma16816(acc1[j], xh, bl);
                mma16816(acc1[j], xl, bh);
                mma16816(acc1[j + 1], xh, bh + 2);
                mma16816(acc1[j + 1], xh, bl + 2);
                mma16816(acc1[j + 1], xl, bh + 2);
            }
        }
        if (c < 31) {
            STORE_XA((c + 1) & 1);
            if (c < 30) LOAD_XA((c + 2) * 64);
        }
        __syncthreads();
    }

    // ===== H -> SMEM bf16 hi/lo =====
    {
        char* hh = smc + SM_HHI;
        char* hl = smc + SM_HLO;
#pragma unroll
        for (int j = 0; j < 8; ++j) {
            uint32_t hi, lo;
            split2(acc1[j][0], acc1[j][1], hi, lo);
            uint32_t off = swz((uint32_t)(m0 + g) * 128 + (j * 8 + 2 * tq) * 2);
            *(uint32_t*)(hh + off) = hi;
            *(uint32_t*)(hl + off) = lo;
            split2(acc1[j][2], acc1[j][3], hi, lo);
            uint32_t off2 = swz((uint32_t)(m0 + g + 8) * 128 + (j * 8 + 2 * tq) * 2);
            *(uint32_t*)(hh + off2) = hi;
            *(uint32_t*)(hl + off2) = lo;
        }
    }

    // ===== stage 2: O[128,2048] = H[128,64] * B_e^T, 16 n-chunks of 128 =====
    const int fn = tid >> 1, fh = tid & 1;   // B fill: n-row, r-half
    float4 vb[8];

#define LOAD_B(N0)                                                             \
    do {                                                                       \
        const float* src = Brow + (size_t)((N0) + fn) * RNK + fh * 32;         \
        _Pragma("unroll") for (int i = 0; i < 8; ++i) vb[i] =                  \
            *(const float4*)(src + i * 4);                                     \
    } while (0)

#define STORE_B(BUF)                                                           \
    do {                                                                       \
        char* bh_ = smc + SM_XA0 + (BUF) * 32768;                              \
        char* bl_ = bh_ + 16384;                                               \
        uint32_t rb = (uint32_t)fn * 128 + (uint32_t)fh * 64;                  \
        _Pragma("unroll") for (int i = 0; i < 8; ++i) {                        \
            uint32_t h0, l0, h1, l1;                                           \
            split2(vb[i].x, vb[i].y, h0, l0);                                  \
            split2(vb[i].z, vb[i].w, h1, l1);                                  \
            uint32_t off = swz(rb + i * 8);                                    \
            *(uint2*)(bh_ + off) = make_uint2(h0, h1);                         \
            *(uint2*)(bl_ + off) = make_uint2(l0, l1);                         \
        }                                                                      \
    } while (0)

    LOAD_B(0);
    STORE_B(0);
    __syncthreads();
    LOAD_B(128);

    const int t_g = tok[m0 + g];
    const int t_g8 = tok[m0 + g + 8];
    float* out_g = out + (size_t)(t_g < 0 ? 0 : t_g) * DIM + 2 * tq;
    float* out_g8 = out + (size_t)(t_g8 < 0 ? 0 : t_g8) * DIM + 2 * tq;

    for (int nc = 0; nc < 16; ++nc) {
        float acc2[16][4];
#pragma unroll
        for (int j = 0; j < 16; ++j)
#pragma unroll
            for (int q = 0; q < 4; ++q) acc2[j][q] = 0.f;

        const uint32_t bb = sbu + SM_XA0 + (uint32_t)(nc & 1) * 32768;
        const uint32_t hbu = sbu + SM_HHI;
#pragma unroll
        for (int kk = 0; kk < 4; ++kk) {
            uint32_t ha[4], hl[4];
            uint32_t hoff = swz(xrow_off + kk * 32);
            ldm_x4(hbu + hoff, ha);
            ldm_x4(hbu + (SM_HLO - SM_HHI) + hoff, hl);
#pragma unroll
            for (int j = 0; j < 16; j += 2) {
                uint32_t bh[4], bl[4];
                uint32_t boff = swz(brow4_off + j * 1024 + kk * 32);
                ldm_x4(bb + boff, bh);
                ldm_x4(bb + 16384 + boff, bl);
                mma16816(acc2[j], ha, bh);
                mma16816(acc2[j], ha, bl);
                mma16816(acc2[j], hl, bh);
                mma16816(acc2[j + 1], ha, bh + 2);
                mma16816(acc2[j + 1], ha, bl + 2);
                mma16816(acc2[j + 1], hl, bh + 2);
            }
        }

        // epilogue: direct STG.64, 4 lanes cover one 32B sector
        const int n0 = nc * 128;
#pragma unroll
        for (int j = 0; j < 16; ++j) {
            int n = n0 + j * 8;
            if (t_g >= 0) *(float2*)(out_g + n) = make_float2(acc2[j][0], acc2[j][1]);
            if (t_g8 >= 0) *(float2*)(out_g8 + n) = make_float2(acc2[j][2], acc2[j][3]);
        }

        if (nc < 15) {
            STORE_B((nc + 1) & 1);
            if (nc < 14) LOAD_B((nc + 2) * 128);
        }
        __syncthreads();
    }
}

// ---------------- launch ----------------
extern "C" void kernel_launch(void* const* d_in, const int* in_sizes, int n_in,
                              void* d_out, int out_size) {
    const float* x  = (const float*)d_in[0];   // [B,S,D]
    const float* Aw = (const float*)d_in[1];   // [E,R,D]
    const float* Bw = (const float*)d_in[2];   // [E,D,R]
    const int*   ti = (const int*)d_in[3];     // [B,S]
    float* out = (float*)d_out;
    (void)in_sizes; (void)n_in; (void)out_size;

    static int smem_set = 0;
    if (!smem_set) {
        cudaFuncSetAttribute(k_main, cudaFuncAttributeMaxDynamicSharedMemorySize, SMEM_BYTES);
        smem_set = 1;
    }

    k_sort<<<1, 1024>>>(ti);
    dim3 grid(NTOK / TM, E_N, 1);
    k_main<<<grid, NTHR, SMEM_BYTES>>>(x, Aw, Bw, out);
}

// round 5
// speedup vs baseline: 3.7982x; 1.0664x over previous
#include <cuda_runtime.h>
#include <cuda_bf16.h>
#include <cstdint>

// Problem constants (E=8, R=64, B=4, S=4096, D=2048)
#define E_N   8
#define RNK   64
#define DIM   2048
#define NTOK  16384
#define TM    128
#define NTHR  256

// ---------------- device scratch ----------------
__device__ int g_count[E_N];
__device__ int g_offset[E_N];
__device__ int g_tokens[NTOK];

// ---------------- helpers ----------------
__device__ __forceinline__ uint32_t smem_u32(const void* p) {
    uint32_t a;
    asm("{ .reg .u64 t; cvta.to.shared.u64 t, %1; cvt.u32.u64 %0, t; }" : "=r"(a) : "l"(p));
    return a;
}
__device__ __forceinline__ uint32_t swz(uint32_t o) { return o ^ ((o >> 3) & 0x70); }

// split fp32 pair -> packed bf16 hi-pair + lo-pair
__device__ __forceinline__ void split2(float a, float b, uint32_t& hi, uint32_t& lo) {
    __nv_bfloat16 ha = __float2bfloat16_rn(a), hb = __float2bfloat16_rn(b);
    float ra = a - __bfloat162float(ha), rb = b - __bfloat162float(hb);
    __nv_bfloat16 la = __float2bfloat16_rn(ra), lb = __float2bfloat16_rn(rb);
    hi = ((uint32_t)__bfloat16_as_ushort(hb) << 16) | (uint32_t)__bfloat16_as_ushort(ha);
    lo = ((uint32_t)__bfloat16_as_ushort(lb) << 16) | (uint32_t)__bfloat16_as_ushort(la);
}

__device__ __forceinline__ void ldm_x4(uint32_t a, uint32_t r[4]) {
    asm volatile("ldmatrix.sync.aligned.m8n8.x4.shared.b16 {%0,%1,%2,%3}, [%4];"
                 : "=r"(r[0]), "=r"(r[1]), "=r"(r[2]), "=r"(r[3]) : "r"(a));
}
__device__ __forceinline__ void mma16816(float* c, const uint32_t* a, const uint32_t* b) {
    asm volatile("mma.sync.aligned.m16n8k16.row.col.f32.bf16.bf16.f32 "
                 "{%0,%1,%2,%3}, {%4,%5,%6,%7}, {%8,%9}, {%0,%1,%2,%3};"
                 : "+f"(c[0]), "+f"(c[1]), "+f"(c[2]), "+f"(c[3])
                 : "r"(a[0]), "r"(a[1]), "r"(a[2]), "r"(a[3]), "r"(b[0]), "r"(b[1]));
}

// ---------------- SMEM layout (bytes) ----------------
// 64    : tok[128]
// 1024  : stage1 A bufs: buf {Ahi 8K, Alo 8K} = 16K; buf0 @1024, buf1 @17408 (end 33792)
// stage2 B bufs (reuse A region): buf {Bhi 16K, Blo 16K} = 32K; buf0 @1024, buf1 @33792 (end 66560)
// 66560 : Hhi 16K ; 82944 : Hlo 16K (end 99328)
#define SM_TOK    64
#define SM_AB0    1024
#define AB_STRIDE 16384
#define SM_B0     1024
#define B_STRIDE  32768
#define SM_HHI    66560
#define SM_HLO    82944
#define SMEM_BYTES 99328

// ---------------- sort kernel (single CTA) ----------------
__global__ void __launch_bounds__(1024) k_sort(const int* __restrict__ ti) {
    __shared__ int sc[E_N];
    __shared__ int sb[E_N];
    const int tid = threadIdx.x;
    const int lane = tid & 31;
    if (tid < E_N) sc[tid] = 0;
    __syncthreads();
    for (int t = tid; t < NTOK; t += 1024) {
        int e = ti[t];
        unsigned mask = __match_any_sync(0xffffffffu, e);
        int leader = __ffs(mask) - 1;
        if (lane == leader) atomicAdd(&sc[e], __popc(mask));
    }
    __syncthreads();
    if (tid == 0) {
        int acc = 0;
        for (int e = 0; e < E_N; ++e) {
            g_count[e] = sc[e];
            g_offset[e] = acc;
            sb[e] = acc;
            acc += sc[e];
        }
    }
    __syncthreads();
    for (int t = tid; t < NTOK; t += 1024) {
        int e = ti[t];
        unsigned mask = __match_any_sync(0xffffffffu, e);
        int leader = __ffs(mask) - 1;
        int prior = __popc(mask & ((1u << lane) - 1));
        int base = 0;
        if (lane == leader) base = atomicAdd(&sb[e], __popc(mask));
        base = __shfl_sync(0xffffffffu, base, leader);
        g_tokens[base + prior] = t;
    }
}

// ---------------- main kernel ----------------
__global__ void __launch_bounds__(NTHR, 1)
k_main(const float* __restrict__ x,
       const float* __restrict__ Aw,
       const float* __restrict__ Bw,
       float* __restrict__ out) {
    const int e = blockIdx.y;
    const int cnt = g_count[e];
    const int mstart = blockIdx.x * TM;
    if (mstart >= cnt) return;
    const int base = g_offset[e];

    extern __shared__ char smc[];
    const uint32_t sbu = smem_u32(smc);
    const int tid = threadIdx.x;
    const int wid = tid >> 5;
    const int lane = tid & 31;
    const int mg = wid >> 1;     // m-group: rows [mg*32, mg*32+32)
    const int ng = wid & 1;      // n-group
    const int g = lane >> 2;
    const int tq = lane & 3;
    int* tok = (int*)(smc + SM_TOK);

    if (tid < TM) {
        int i = mstart + tid;
        tok[tid] = (i < cnt) ? g_tokens[base + i] : -1;
    }
    __syncthreads();

    const float* Arow = Aw + (size_t)e * RNK * DIM;
    const float* Brow = Bw + (size_t)e * DIM * RNK;

    // per-warp token rows: i -> row mg*32 + i*8 + g  (mt = i>>1)
    int tko[4];
    bool tv[4];
    const float* xr[4];
#pragma unroll
    for (int i = 0; i < 4; ++i) {
        int t = tok[mg * 32 + i * 8 + g];
        tv[i] = (t >= 0);
        tko[i] = tv[i] ? t : 0;
        xr[i] = x + (size_t)tko[i] * DIM;
    }

    // ldmatrix lane patterns (pre-swizzle, relative to tile row base)
    const uint32_t bpair = (uint32_t)((lane & 7) + ((lane >> 4) << 3)) * 128 +
                           (uint32_t)((lane >> 3) & 1) * 16;          // 16-row n-pair
    const uint32_t apat  = (uint32_t)(lane & 15) * 128 + (uint32_t)(lane >> 4) * 16; // m16 A-op

    // A fill mapping (64 r-rows x 64 k fp32 per chunk)
    const int fr = tid >> 2, fq = tid & 3;
    float4 va[4];

#define LOAD_A(K0)                                                              \
    do {                                                                        \
        _Pragma("unroll") for (int i = 0; i < 4; ++i) va[i] =                   \
            *(const float4*)(Arow + (size_t)fr * DIM + (K0) + fq * 16 + i * 4); \
    } while (0)

#define STORE_A(BUF)                                                            \
    do {                                                                        \
        char* ah = smc + SM_AB0 + (BUF) * AB_STRIDE;                            \
        char* al = ah + 8192;                                                   \
        uint32_t rb = (uint32_t)fr * 128 + (uint32_t)fq * 32;                   \
        _Pragma("unroll") for (int i = 0; i < 4; ++i) {                         \
            uint32_t h0, l0, h1, l1;                                            \
            split2(va[i].x, va[i].y, h0, l0);                                   \
            split2(va[i].z, va[i].w, h1, l1);                                   \
            uint32_t off = swz(rb + i * 8);                                     \
            *(uint2*)(ah + off) = make_uint2(h0, h1);                           \
            *(uint2*)(al + off) = make_uint2(l0, l1);                           \
        }                                                                       \
    } while (0)

    // ===== stage 1: H[128,64] = X[128,2048] * A_e^T =====
    float acc1[2][4][4];
#pragma unroll
    for (int mt = 0; mt < 2; ++mt)
#pragma unroll
        for (int j = 0; j < 4; ++j)
#pragma unroll
            for (int q = 0; q < 4; ++q) acc1[mt][j][q] = 0.f;

    LOAD_A(0);
    STORE_A(0);
    __syncthreads();
    LOAD_A(64);

    // X raw register prefetch (fragment layout, direct from GMEM)
    float2 raw[2][8];
#define PFX(BUF, KG)                                                            \
    do {                                                                        \
        raw[BUF][0] = *(const float2*)(xr[0] + (KG) + 2 * tq);                  \
        raw[BUF][1] = *(const float2*)(xr[1] + (KG) + 2 * tq);                  \
        raw[BUF][2] = *(const float2*)(xr[0] + (KG) + 8 + 2 * tq);              \
        raw[BUF][3] = *(const float2*)(xr[1] + (KG) + 8 + 2 * tq);              \
        raw[BUF][4] = *(const float2*)(xr[2] + (KG) + 2 * tq);                  \
        raw[BUF][5] = *(const float2*)(xr[3] + (KG) + 2 * tq);                  \
        raw[BUF][6] = *(const float2*)(xr[2] + (KG) + 8 + 2 * tq);              \
        raw[BUF][7] = *(const float2*)(xr[3] + (KG) + 8 + 2 * tq);              \
    } while (0)

    PFX(0, 0);
    for (int c = 0; c < 32; ++c) {
        const uint32_t ahB = sbu + SM_AB0 + (uint32_t)(c & 1) * AB_STRIDE;
#pragma unroll
        for (int kk = 0; kk < 4; ++kk) {
            int kg = c * 64 + kk * 16 + 16;
            if (kg < DIM) {
                if ((kk & 1) == 0) PFX(1, kg); else PFX(0, kg);
            }
            const float2* rw = raw[kk & 1];
            uint32_t xh0[4], xl0[4], xh1[4], xl1[4];
            split2(rw[0].x, rw[0].y, xh0[0], xl0[0]);
            split2(rw[1].x, rw[1].y, xh0[1], xl0[1]);
            split2(rw[2].x, rw[2].y, xh0[2], xl0[2]);
            split2(rw[3].x, rw[3].y, xh0[3], xl0[3]);
            split2(rw[4].x, rw[4].y, xh1[0], xl1[0]);
            split2(rw[5].x, rw[5].y, xh1[1], xl1[1]);
            split2(rw[6].x, rw[6].y, xh1[2], xl1[2]);
            split2(rw[7].x, rw[7].y, xh1[3], xl1[3]);
#pragma unroll
            for (int jj = 0; jj < 2; ++jj) {
                uint32_t bh[4], bl[4];
                uint32_t ao = swz((uint32_t)(ng * 32 + jj * 16) * 128 + bpair + kk * 32);
                ldm_x4(ahB + ao, bh);
                ldm_x4(ahB + 8192 + ao, bl);
                mma16816(acc1[0][jj * 2], xh0, bh);
                mma16816(acc1[0][jj * 2], xh0, bl);
                mma16816(acc1[0][jj * 2], xl0, bh);
                mma16816(acc1[0][jj * 2 + 1], xh0, bh + 2);
                mma16816(acc1[0][jj * 2 + 1], xh0, bl + 2);
                mma16816(acc1[0][jj * 2 + 1], xl0, bh + 2);
                mma16816(acc1[1][jj * 2], xh1, bh);
                mma16816(acc1[1][jj * 2], xh1, bl);
                mma16816(acc1[1][jj * 2], xl1, bh);
                mma16816(acc1[1][jj * 2 + 1], xh1, bh + 2);
                mma16816(acc1[1][jj * 2 + 1], xh1, bl + 2);
                mma16816(acc1[1][jj * 2 + 1], xl1, bh + 2);
            }
        }
        if (c < 31) {
            STORE_A((c + 1) & 1);
            if (c < 30) LOAD_A((c + 2) * 64);
        }
        __syncthreads();
    }

    // ===== stage 2 fills (B) =====
    const int fn = tid >> 1, fh = tid & 1;
    float4 vb[8];

#define LOAD_B(N0)                                                              \
    do {                                                                        \
        const float* src = Brow + (size_t)((N0) + fn) * RNK + fh * 32;          \
        _Pragma("unroll") for (int i = 0; i < 8; ++i) vb[i] =                   \
            *(const float4*)(src + i * 4);                                      \
    } while (0)

#define STORE_B(BUF)                                                            \
    do {                                                                        \
        char* bh_ = smc + SM_B0 + (BUF) * B_STRIDE;                             \
        char* bl_ = bh_ + 16384;                                                \
        uint32_t rb = (uint32_t)fn * 128 + (uint32_t)fh * 64;                   \
        _Pragma("unroll") for (int i = 0; i < 8; ++i) {                         \
            uint32_t h0, l0, h1, l1;                                            \
            split2(vb[i].x, vb[i].y, h0, l0);                                   \
            split2(vb[i].z, vb[i].w, h1, l1);                                   \
            uint32_t off = swz(rb + i * 8);                                     \
            *(uint2*)(bh_ + off) = make_uint2(h0, h1);                          \
            *(uint2*)(bl_ + off) = make_uint2(l0, l1);                          \
        }                                                                       \
    } while (0)

    LOAD_B(0);   // start GMEM reads early

    // ===== H -> SMEM bf16 hi/lo (fragment-consistent layout) =====
    {
        char* hh = smc + SM_HHI;
        char* hl = smc + SM_HLO;
#pragma unroll
        for (int mt = 0; mt < 2; ++mt)
#pragma unroll
            for (int j = 0; j < 4; ++j) {
                int col = ng * 32 + j * 8 + 2 * tq;
                int r0 = mg * 32 + mt * 16 + g;
                uint32_t hi, lo;
                split2(acc1[mt][j][0], acc1[mt][j][1], hi, lo);
                uint32_t off = swz((uint32_t)r0 * 128 + (uint32_t)col * 2);
                *(uint32_t*)(hh + off) = hi;
                *(uint32_t*)(hl + off) = lo;
                split2(acc1[mt][j][2], acc1[mt][j][3], hi, lo);
                uint32_t off2 = swz((uint32_t)(r0 + 8) * 128 + (uint32_t)col * 2);
                *(uint32_t*)(hh + off2) = hi;
                *(uint32_t*)(hl + off2) = lo;
            }
    }
    STORE_B(0);
    __syncthreads();

    // preload ALL H fragments into registers (reused across all 16 n-chunks)
    uint32_t hfh[2][4][4], hfl[2][4][4];
#pragma unroll
    for (int mt = 0; mt < 2; ++mt)
#pragma unroll
        for (int kk = 0; kk < 4; ++kk) {
            uint32_t ho = swz((uint32_t)(mg * 32 + mt * 16) * 128 + apat + kk * 32);
            ldm_x4(sbu + SM_HHI + ho, hfh[mt][kk]);
            ldm_x4(sbu + SM_HLO + ho, hfl[mt][kk]);
        }

    LOAD_B(128);

    // ===== stage 2: O[128,2048] = H[128,64] * B_e^T, 16 n-chunks of 128 =====
    for (int nc = 0; nc < 16; ++nc) {
        float acc2[2][8][4];
#pragma unroll
        for (int mt = 0; mt < 2; ++mt)
#pragma unroll
            for (int j = 0; j < 8; ++j)
#pragma unroll
                for (int q = 0; q < 4; ++q) acc2[mt][j][q] = 0.f;

        const uint32_t bbB = sbu + SM_B0 + (uint32_t)(nc & 1) * B_STRIDE;
#pragma unroll
        for (int kk = 0; kk < 4; ++kk) {
#pragma unroll
            for (int jj = 0; jj < 4; ++jj) {
                uint32_t bh[4], bl[4];
                uint32_t bo = swz((uint32_t)(ng * 64 + jj * 16) * 128 + bpair + kk * 32);
                ldm_x4(bbB + bo, bh);
                ldm_x4(bbB + 16384 + bo, bl);
#pragma unroll
                for (int mt = 0; mt < 2; ++mt) {
                    mma16816(acc2[mt][jj * 2], hfh[mt][kk], bh);
                    mma16816(acc2[mt][jj * 2], hfh[mt][kk], bl);
                    mma16816(acc2[mt][jj * 2], hfl[mt][kk], bh);
                    mma16816(acc2[mt][jj * 2 + 1], hfh[mt][kk], bh + 2);
                    mma16816(acc2[mt][jj * 2 + 1], hfh[mt][kk], bl + 2);
                    mma16816(acc2[mt][jj * 2 + 1], hfl[mt][kk], bh + 2);
                }
            }
        }

        // epilogue: direct STG.64
        const int nb0 = nc * 128 + ng * 64 + 2 * tq;
#pragma unroll
        for (int mt = 0; mt < 2; ++mt)
#pragma unroll
            for (int j = 0; j < 8; ++j) {
                int colo = nb0 + j * 8;
                if (tv[mt * 2])
                    *(float2*)(out + (size_t)tko[mt * 2] * DIM + colo) =
                        make_float2(acc2[mt][j][0], acc2[mt][j][1]);
                if (tv[mt * 2 + 1])
                    *(float2*)(out + (size_t)tko[mt * 2 + 1] * DIM + colo) =
                        make_float2(acc2[mt][j][2], acc2[mt][j][3]);
            }

        if (nc < 15) {
            STORE_B((nc + 1) & 1);
            if (nc < 14) LOAD_B((nc + 2) * 128);
        }
        __syncthreads();
    }
}

// ---------------- launch ----------------
extern "C" void kernel_launch(void* const* d_in, const int* in_sizes, int n_in,
                              void* d_out, int out_size) {
    const float* x  = (const float*)d_in[0];   // [B,S,D]
    const float* Aw = (const float*)d_in[1];   // [E,R,D]
    const float* Bw = (const float*)d_in[2];   // [E,D,R]
    const int*   ti = (const int*)d_in[3];     // [B,S]
    float* out = (float*)d_out;
    (void)in_sizes; (void)n_in; (void)out_size;

    static int smem_set = 0;
    if (!smem_set) {
        cudaFuncSetAttribute(k_main, cudaFuncAttributeMaxDynamicSharedMemorySize, SMEM_BYTES);
        smem_set = 1;
    }

    k_sort<<<1, 1024>>>(ti);
    dim3 grid(NTOK / TM, E_N, 1);
    k_main<<<grid, NTHR, SMEM_BYTES>>>(x, Aw, Bw, out);
}

// round 8
// speedup vs baseline: 3.9608x; 1.0428x over previous
#include <cuda_runtime.h>
#include <cuda_bf16.h>
#include <cstdint>

// Problem constants (E=8, R=64, B=4, S=4096, D=2048)
#define E_N   8
#define RNK   64
#define DIM   2048
#define NTOK  16384
#define TM    128
#define NTHR  512

// ---------------- device scratch ----------------
__device__ int g_count[E_N];
__device__ int g_offset[E_N];
__device__ int g_tokens[NTOK];

// ---------------- helpers ----------------
__device__ __forceinline__ uint32_t smem_u32(const void* p) {
    uint32_t a;
    asm("{ .reg .u64 t; cvta.to.shared.u64 t, %1; cvt.u32.u64 %0, t; }" : "=r"(a) : "l"(p));
    return a;
}
__device__ __forceinline__ uint32_t swz(uint32_t o) { return o ^ ((o >> 3) & 0x70); }

// split fp32 pair -> packed bf16 hi-pair + lo-pair
__device__ __forceinline__ void split2(float a, float b, uint32_t& hi, uint32_t& lo) {
    __nv_bfloat16 ha = __float2bfloat16_rn(a), hb = __float2bfloat16_rn(b);
    float ra = a - __bfloat162float(ha), rb = b - __bfloat162float(hb);
    __nv_bfloat16 la = __float2bfloat16_rn(ra), lb = __float2bfloat16_rn(rb);
    hi = ((uint32_t)__bfloat16_as_ushort(hb) << 16) | (uint32_t)__bfloat16_as_ushort(ha);
    lo = ((uint32_t)__bfloat16_as_ushort(lb) << 16) | (uint32_t)__bfloat16_as_ushort(la);
}

__device__ __forceinline__ void ldm_x4(uint32_t a, uint32_t r[4]) {
    asm volatile("ldmatrix.sync.aligned.m8n8.x4.shared.b16 {%0,%1,%2,%3}, [%4];"
                 : "=r"(r[0]), "=r"(r[1]), "=r"(r[2]), "=r"(r[3]) : "r"(a));
}
__device__ __forceinline__ void mma16816(float* c, const uint32_t* a, const uint32_t* b) {
    asm volatile("mma.sync.aligned.m16n8k16.row.col.f32.bf16.bf16.f32 "
                 "{%0,%1,%2,%3}, {%4,%5,%6,%7}, {%8,%9}, {%0,%1,%2,%3};"
                 : "+f"(c[0]), "+f"(c[1]), "+f"(c[2]), "+f"(c[3])
                 : "r"(a[0]), "r"(a[1]), "r"(a[2]), "r"(a[3]), "r"(b[0]), "r"(b[1]));
}

// ---------------- SMEM layout (bytes) ----------------
// 64    : tok[128]
// 1024  : stage1 A bufs: buf {Ahi 8K, Alo 8K} = 16K; buf0 @1024, buf1 @17408 (end 33792)
// stage2 B bufs (reuse): buf {Bhi 16K, Blo 16K} = 32K; buf0 @1024, buf1 @33792 (end 66560)
// 66560 : Hhi 16K ; 82944 : Hlo 16K (end 99328)
#define SM_TOK    64
#define SM_AB0    1024
#define AB_STRIDE 16384
#define SM_B0     1024
#define B_STRIDE  32768
#define SM_HHI    66560
#define SM_HLO    82944
#define SMEM_BYTES 99328

// ---------------- sort kernel (single CTA) ----------------
__global__ void __launch_bounds__(1024) k_sort(const int* __restrict__ ti) {
    __shared__ int sc[E_N];
    __shared__ int sb[E_N];
    const int tid = threadIdx.x;
    const int lane = tid & 31;
    if (tid < E_N) sc[tid] = 0;
    __syncthreads();
    for (int t = tid; t < NTOK; t += 1024) {
        int e = ti[t];
        unsigned mask = __match_any_sync(0xffffffffu, e);
        int leader = __ffs(mask) - 1;
        if (lane == leader) atomicAdd(&sc[e], __popc(mask));
    }
    __syncthreads();
    if (tid == 0) {
        int acc = 0;
        for (int e = 0; e < E_N; ++e) {
            g_count[e] = sc[e];
            g_offset[e] = acc;
            sb[e] = acc;
            acc += sc[e];
        }
    }
    __syncthreads();
    for (int t = tid; t < NTOK; t += 1024) {
        int e = ti[t];
        unsigned mask = __match_any_sync(0xffffffffu, e);
        int leader = __ffs(mask) - 1;
        int prior = __popc(mask & ((1u << lane) - 1));
        int base = 0;
        if (lane == leader) base = atomicAdd(&sb[e], __popc(mask));
        base = __shfl_sync(0xffffffffu, base, leader);
        g_tokens[base + prior] = t;
    }
}

// ---------------- main kernel ----------------
__global__ void __launch_bounds__(NTHR, 1)
k_main(const float* __restrict__ x,
       const float* __restrict__ Aw,
       const float* __restrict__ Bw,
       float* __restrict__ out) {
    const int e = blockIdx.y;
    const int cnt = g_count[e];
    const int mstart = blockIdx.x * TM;
    if (mstart >= cnt) return;
    const int base = g_offset[e];

    extern __shared__ char smc[];
    const uint32_t sbu = smem_u32(smc);
    const int tid = threadIdx.x;
    const int wid = tid >> 5;
    const int lane = tid & 31;
    const int g = lane >> 2;
    const int tq = lane & 3;
    // stage-1 warp tile: m16 x n32
    const int s1mg = wid >> 1;   // rows s1mg*16..+16
    const int s1ng = wid & 1;    // cols s1ng*32..+32
    // stage-2 warp tile: m32 x n32
    const int s2mg = wid >> 2;   // rows s2mg*32..+32
    const int s2ng = wid & 3;    // chunk cols s2ng*32..+32
    int* tok = (int*)(smc + SM_TOK);

    if (tid < TM) {
        int i = mstart + tid;
        tok[tid] = (i < cnt) ? g_tokens[base + i] : -1;
    }
    __syncthreads();

    const float* Arow = Aw + (size_t)e * RNK * DIM;
    const float* Brow = Bw + (size_t)e * DIM * RNK;

    // stage-1 X rows for this warp (fragment layout)
    const int t1a = tok[s1mg * 16 + g];
    const int t1b = tok[s1mg * 16 + 8 + g];
    const float* xr0 = x + (size_t)(t1a < 0 ? 0 : t1a) * DIM;
    const float* xr1 = x + (size_t)(t1b < 0 ? 0 : t1b) * DIM;

    // ldmatrix lane patterns (pre-swizzle, relative to tile row base)
    const uint32_t bpair = (uint32_t)((lane & 7) + ((lane >> 4) << 3)) * 128 +
                           (uint32_t)((lane >> 3) & 1) * 16;          // 16-row n-pair
    const uint32_t apat  = (uint32_t)(lane & 15) * 128 + (uint32_t)(lane >> 4) * 16; // m16 A-op

    // A fill mapping: 64 r-rows x 64 k fp32 per chunk, 512 threads x 2 float4
    const int fr = tid >> 3, fq = tid & 7;
    float4 va[2];

#define LOAD_A(K0)                                                              \
    do {                                                                        \
        _Pragma("unroll") for (int i = 0; i < 2; ++i) va[i] =                   \
            *(const float4*)(Arow + (size_t)fr * DIM + (K0) + fq * 8 + i * 4);  \
    } while (0)

#define STORE_A(BUF)                                                            \
    do {                                                                        \
        char* ah = smc + SM_AB0 + (BUF) * AB_STRIDE;                            \
        char* al = ah + 8192;                                                   \
        uint32_t rb = (uint32_t)fr * 128 + (uint32_t)fq * 16;                   \
        _Pragma("unroll") for (int i = 0; i < 2; ++i) {                         \
            uint32_t h0, l0, h1, l1;                                            \
            split2(va[i].x, va[i].y, h0, l0);                                   \
            split2(va[i].z, va[i].w, h1, l1);                                   \
            uint32_t off = swz(rb + i * 8);                                     \
            *(uint2*)(ah + off) = make_uint2(h0, h1);                           \
            *(uint2*)(al + off) = make_uint2(l0, l1);                           \
        }                                                                       \
    } while (0)

    // ===== stage 1: H[128,64] = X[128,2048] * A_e^T =====
    float acc1[4][4];
#pragma unroll
    for (int j = 0; j < 4; ++j)
#pragma unroll
        for (int q = 0; q < 4; ++q) acc1[j][q] = 0.f;

    LOAD_A(0);
    STORE_A(0);
    __syncthreads();
    LOAD_A(64);

    // X raw register prefetch (A-fragment layout, direct from GMEM)
    float2 raw[2][4];
#define PFX(BUF, KG)                                                            \
    do {                                                                        \
        raw[BUF][0] = *(const float2*)(xr0 + (KG) + 2 * tq);                    \
        raw[BUF][1] = *(const float2*)(xr1 + (KG) + 2 * tq);                    \
        raw[BUF][2] = *(const float2*)(xr0 + (KG) + 8 + 2 * tq);                \
        raw[BUF][3] = *(const float2*)(xr1 + (KG) + 8 + 2 * tq);                \
    } while (0)

    PFX(0, 0);
    for (int c = 0; c < 32; ++c) {
        const uint32_t ahB = sbu + SM_AB0 + (uint32_t)(c & 1) * AB_STRIDE;
#pragma unroll
        for (int kk = 0; kk < 4; ++kk) {
            int kg = c * 64 + kk * 16 + 16;
            if (kg < DIM) {
                if ((kk & 1) == 0) PFX(1, kg); else PFX(0, kg);
            }
            const float2* rw = raw[kk & 1];
            uint32_t xh[4], xl[4];
            split2(rw[0].x, rw[0].y, xh[0], xl[0]);
            split2(rw[1].x, rw[1].y, xh[1], xl[1]);
            split2(rw[2].x, rw[2].y, xh[2], xl[2]);
            split2(rw[3].x, rw[3].y, xh[3], xl[3]);
#pragma unroll
            for (int jj = 0; jj < 2; ++jj) {
                uint32_t bh[4], bl[4];
                uint32_t ao = swz((uint32_t)(s1ng * 32 + jj * 16) * 128 + bpair + kk * 32);
                ldm_x4(ahB + ao, bh);
                ldm_x4(ahB + 8192 + ao, bl);
                mma16816(acc1[jj * 2], xh, bh);
                mma16816(acc1[jj * 2], xh, bl);
                mma16816(acc1[jj * 2], xl, bh);
                mma16816(acc1[jj * 2 + 1], xh, bh + 2);
                mma16816(acc1[jj * 2 + 1], xh, bl + 2);
                mma16816(acc1[jj * 2 + 1], xl, bh + 2);
            }
        }
        if (c < 31) {
            STORE_A((c + 1) & 1);
            if (c < 30) LOAD_A((c + 2) * 64);
        }
        __syncthreads();
    }

    // ===== stage 2 fills (B): 128n x 64r fp32 per chunk, 512 threads x 4 float4 =====
    const int fn = tid >> 2, fh = tid & 3;
    float4 vb[4];

#define LOAD_B(N0)                                                              \
    do {                                                                        \
        const float* src = Brow + (size_t)((N0) + fn) * RNK + fh * 16;          \
        _Pragma("unroll") for (int i = 0; i < 4; ++i) vb[i] =                   \
            *(const float4*)(src + i * 4);                                      \
    } while (0)

#define STORE_B(BUF)                                                            \
    do {                                                                        \
        char* bh_ = smc + SM_B0 + (BUF) * B_STRIDE;                             \
        char* bl_ = bh_ + 16384;                                                \
        uint32_t rb = (uint32_t)fn * 128 + (uint32_t)fh * 32;                   \
        _Pragma("unroll") for (int i = 0; i < 4; ++i) {                         \
            uint32_t h0, l0, h1, l1;                                            \
            split2(vb[i].x, vb[i].y, h0, l0);                                   \
            split2(vb[i].z, vb[i].w, h1, l1);                                   \
            uint32_t off = swz(rb + i * 8);                                     \
            *(uint2*)(bh_ + off) = make_uint2(h0, h1);                          \
            *(uint2*)(bl_ + off) = make_uint2(l0, l1);                          \
        }                                                                       \
    } while (0)

    LOAD_B(0);   // start GMEM reads early

    // ===== H -> SMEM bf16 hi/lo (fragment-consistent layout) =====
    {
        char* hh = smc + SM_HHI;
        char* hl = smc + SM_HLO;
#pragma unroll
        for (int j = 0; j < 4; ++j) {
            int col = s1ng * 32 + j * 8 + 2 * tq;
            int r0 = s1mg * 16 + g;
            uint32_t hi, lo;
            split2(acc1[j][0], acc1[j][1], hi, lo);
            uint32_t off = swz((uint32_t)r0 * 128 + (uint32_t)col * 2);
            *(uint32_t*)(hh + off) = hi;
            *(uint32_t*)(hl + off) = lo;
            split2(acc1[j][2], acc1[j][3], hi, lo);
            uint32_t off2 = swz((uint32_t)(r0 + 8) * 128 + (uint32_t)col * 2);
            *(uint32_t*)(hh + off2) = hi;
            *(uint32_t*)(hl + off2) = lo;
        }
    }
    STORE_B(0);
    __syncthreads();

    // preload ALL H fragments into registers (reused across all 16 n-chunks)
    uint32_t hfh[2][4][4], hfl[2][4][4];
#pragma unroll
    for (int mt = 0; mt < 2; ++mt)
#pragma unroll
        for (int kk = 0; kk < 4; ++kk) {
            uint32_t ho = swz((uint32_t)(s2mg * 32 + mt * 16) * 128 + apat + kk * 32);
            ldm_x4(sbu + SM_HHI + ho, hfh[mt][kk]);
            ldm_x4(sbu + SM_HLO + ho, hfl[mt][kk]);
        }

    // stage-2 output tokens for this warp
    int tko[2][2];
#pragma unroll
    for (int mt = 0; mt < 2; ++mt) {
        tko[mt][0] = tok[s2mg * 32 + mt * 16 + g];
        tko[mt][1] = tok[s2mg * 32 + mt * 16 + 8 + g];
    }

    LOAD_B(128);

    // ===== stage 2: O[128,2048] = H[128,64] * B_e^T, 16 n-chunks of 128 =====
    for (int nc = 0; nc < 16; ++nc) {
        float acc2[2][4][4];
#pragma unroll
        for (int mt = 0; mt < 2; ++mt)
#pragma unroll
            for (int j = 0; j < 4; ++j)
#pragma unroll
                for (int q = 0; q < 4; ++q) acc2[mt][j][q] = 0.f;

        const uint32_t bbB = sbu + SM_B0 + (uint32_t)(nc & 1) * B_STRIDE;
#pragma unroll
        for (int kk = 0; kk < 4; ++kk) {
#pragma unroll
            for (int jj = 0; jj < 2; ++jj) {
                uint32_t bh[4], bl[4];
                uint32_t bo = swz((uint32_t)(s2ng * 32 + jj * 16) * 128 + bpair + kk * 32);
                ldm_x4(bbB + bo, bh);
                ldm_x4(bbB + 16384 + bo, bl);
#pragma unroll
                for (int mt = 0; mt < 2; ++mt) {
                    mma16816(acc2[mt][jj * 2], hfh[mt][kk], bh);
                    mma16816(acc2[mt][jj * 2], hfh[mt][kk], bl);
                    mma16816(acc2[mt][jj * 2], hfl[mt][kk], bh);
                    mma16816(acc2[mt][jj * 2 + 1], hfh[mt][kk], bh + 2);
                    mma16816(acc2[mt][jj * 2 + 1], hfh[mt][kk], bl + 2);
                    mma16816(acc2[mt][jj * 2 + 1], hfl[mt][kk], bh + 2);
                }
            }
        }

        // epilogue: direct STG.64
        const int nb0 = nc * 128 + s2ng * 32 + 2 * tq;
#pragma unroll
        for (int mt = 0; mt < 2; ++mt)
#pragma unroll
            for (int j = 0; j < 4; ++j) {
                int colo = nb0 + j * 8;
                if (tko[mt][0] >= 0)
                    *(float2*)(out + (size_t)tko[mt][0] * DIM + colo) =
                        make_float2(acc2[mt][j][0], acc2[mt][j][1]);
                if (tko[mt][1] >= 0)
                    *(float2*)(out + (size_t)tko[mt][1] * DIM + colo) =
                        make_float2(acc2[mt][j][2], acc2[mt][j][3]);
            }

        if (nc < 15) {
            STORE_B((nc + 1) & 1);
            if (nc < 14) LOAD_B((nc + 2) * 128);
        }
        __syncthreads();
    }
}

// ---------------- launch ----------------
extern "C" void kernel_launch(void* const* d_in, const int* in_sizes, int n_in,
                              void* d_out, int out_size) {
    const float* x  = (const float*)d_in[0];   // [B,S,D]
    const float* Aw = (const float*)d_in[1];   // [E,R,D]
    const float* Bw = (const float*)d_in[2];   // [E,D,R]
    const int*   ti = (const int*)d_in[3];     // [B,S]
    float* out = (float*)d_out;
    (void)in_sizes; (void)n_in; (void)out_size;

    static int smem_set = 0;
    if (!smem_set) {
        cudaFuncSetAttribute(k_main, cudaFuncAttributeMaxDynamicSharedMemorySize, SMEM_BYTES);
        smem_set = 1;
    }

    k_sort<<<1, 1024>>>(ti);
    dim3 grid(NTOK / TM, E_N, 1);
    k_main<<<grid, NTHR, SMEM_BYTES>>>(x, Aw, Bw, out);
}

// round 9
// speedup vs baseline: 4.5961x; 1.1604x over previous
#include <cuda_runtime.h>
#include <cuda_bf16.h>
#include <cstdint>

// Problem constants (E=8, R=64, B=4, S=4096, D=2048)
#define E_N   8
#define RNK   64
#define DIM   2048
#define NTOK  16384
#define TM    128
#define NTHR  512

// ---------------- device scratch ----------------
__device__ int g_count[E_N];
__device__ int g_offset[E_N];
__device__ int g_tokens[NTOK];

// ---------------- helpers ----------------
__device__ __forceinline__ uint32_t smem_u32(const void* p) {
    uint32_t a;
    asm("{ .reg .u64 t; cvta.to.shared.u64 t, %1; cvt.u32.u64 %0, t; }" : "=r"(a) : "l"(p));
    return a;
}
__device__ __forceinline__ uint32_t swz(uint32_t o) { return o ^ ((o >> 3) & 0x70); }

// split fp32 pair -> packed bf16 hi-pair + lo-pair
__device__ __forceinline__ void split2(float a, float b, uint32_t& hi, uint32_t& lo) {
    __nv_bfloat16 ha = __float2bfloat16_rn(a), hb = __float2bfloat16_rn(b);
    float ra = a - __bfloat162float(ha), rb = b - __bfloat162float(hb);
    __nv_bfloat16 la = __float2bfloat16_rn(ra), lb = __float2bfloat16_rn(rb);
    hi = ((uint32_t)__bfloat16_as_ushort(hb) << 16) | (uint32_t)__bfloat16_as_ushort(ha);
    lo = ((uint32_t)__bfloat16_as_ushort(lb) << 16) | (uint32_t)__bfloat16_as_ushort(la);
}

__device__ __forceinline__ void ldm_x4(uint32_t a, uint32_t r[4]) {
    asm volatile("ldmatrix.sync.aligned.m8n8.x4.shared.b16 {%0,%1,%2,%3}, [%4];"
                 : "=r"(r[0]), "=r"(r[1]), "=r"(r[2]), "=r"(r[3]) : "r"(a));
}
__device__ __forceinline__ void mma16816(float* c, const uint32_t* a, const uint32_t* b) {
    asm volatile("mma.sync.aligned.m16n8k16.row.col.f32.bf16.bf16.f32 "
                 "{%0,%1,%2,%3}, {%4,%5,%6,%7}, {%8,%9}, {%0,%1,%2,%3};"
                 : "+f"(c[0]), "+f"(c[1]), "+f"(c[2]), "+f"(c[3])
                 : "r"(a[0]), "r"(a[1]), "r"(a[2]), "r"(a[3]), "r"(b[0]), "r"(b[1]));
}

// ---------------- SMEM layout (bytes) ----------------
// 64     : tok[128]
// 1024   : X bufs fp32 (128 rows x 288B stride) 36864 each; X0@1024, X1@37888 (end 74752)
//          stage2 B bufs reuse X region: {Bhi 16K, Blo 16K}=32K; B0@1024, B1@33792
// 74752  : A bufs {Ahi 8K, Alo 8K}=16K; A0@74752, A1@91136 (end 107520)
// 107520 : Hhi 16K ; 123904 : Hlo 16K (end 140288)
#define SM_TOK    64
#define SM_X0     1024
#define X_STRIDE  36864
#define X_ROWB    288
#define SM_B0     1024
#define B_STRIDE  32768
#define SM_A0     74752
#define A_STRIDE  16384
#define SM_HHI    107520
#define SM_HLO    123904
#define SMEM_BYTES 140288

// ---------------- sort kernel (single CTA) ----------------
__global__ void __launch_bounds__(1024) k_sort(const int* __restrict__ ti) {
    __shared__ int sc[E_N];
    __shared__ int sb[E_N];
    const int tid = threadIdx.x;
    const int lane = tid & 31;
    if (tid < E_N) sc[tid] = 0;
    __syncthreads();
    for (int t = tid; t < NTOK; t += 1024) {
        int e = ti[t];
        unsigned mask = __match_any_sync(0xffffffffu, e);
        int leader = __ffs(mask) - 1;
        if (lane == leader) atomicAdd(&sc[e], __popc(mask));
    }
    __syncthreads();
    if (tid == 0) {
        int acc = 0;
        for (int e = 0; e < E_N; ++e) {
            g_count[e] = sc[e];
            g_offset[e] = acc;
            sb[e] = acc;
            acc += sc[e];
        }
    }
    __syncthreads();
    for (int t = tid; t < NTOK; t += 1024) {
        int e = ti[t];
        unsigned mask = __match_any_sync(0xffffffffu, e);
        int leader = __ffs(mask) - 1;
        int prior = __popc(mask & ((1u << lane) - 1));
        int base = 0;
        if (lane == leader) base = atomicAdd(&sb[e], __popc(mask));
        base = __shfl_sync(0xffffffffu, base, leader);
        g_tokens[base + prior] = t;
    }
}

// ---------------- main kernel ----------------
__global__ void __launch_bounds__(NTHR, 1)
k_main(const float* __restrict__ x,
       const float* __restrict__ Aw,
       const float* __restrict__ Bw,
       float* __restrict__ out) {
    const int e = blockIdx.y;
    const int cnt = g_count[e];
    const int mstart = blockIdx.x * TM;
    if (mstart >= cnt) return;
    const int base = g_offset[e];

    extern __shared__ char smc[];
    const uint32_t sbu = smem_u32(smc);
    const int tid = threadIdx.x;
    const int wid = tid >> 5;
    const int lane = tid & 31;
    const int g = lane >> 2;
    const int tq = lane & 3;
    // stage-1 warp tile: m16 x n32
    const int s1mg = wid >> 1;   // rows s1mg*16..+16
    const int s1ng = wid & 1;    // cols s1ng*32..+32
    // stage-2 warp tile: m32 x n32
    const int s2mg = wid >> 2;   // rows s2mg*32..+32
    const int s2ng = wid & 3;    // chunk cols s2ng*32..+32
    int* tok = (int*)(smc + SM_TOK);

    if (tid < TM) {
        int i = mstart + tid;
        tok[tid] = (i < cnt) ? g_tokens[base + i] : -1;
    }
    __syncthreads();

    const float* Arow = Aw + (size_t)e * RNK * DIM;
    const float* Brow = Bw + (size_t)e * DIM * RNK;

    // ldmatrix lane patterns (pre-swizzle, relative to tile row base)
    const uint32_t bpair = (uint32_t)((lane & 7) + ((lane >> 4) << 3)) * 128 +
                           (uint32_t)((lane >> 3) & 1) * 16;          // 16-row n-pair
    const uint32_t apat  = (uint32_t)(lane & 15) * 128 + (uint32_t)(lane >> 4) * 16; // m16 A-op

    // ---- fill mappings (coalesced full 128B lines per LDG instr) ----
    // X: 128 rows x 64 k fp32 per chunk; thread handles rows {xfr, xfr+64},
    // per row two float4 at k = xfq*4 (+32)
    const int xfr = tid >> 3, xfq = tid & 7;
    const int xt0 = tok[xfr], xt1 = tok[xfr + 64];
    const float* xp0 = x + (size_t)(xt0 < 0 ? 0 : xt0) * DIM;
    const float* xp1 = x + (size_t)(xt1 < 0 ? 0 : xt1) * DIM;
    float4 vx[4];
    // A: 64 rows x 64 k fp32 per chunk; thread row fr, float4 at k = fq*4 + i*32
    const int fr = tid >> 3, fq = tid & 7;
    float4 va[2];

#define LOAD_X(K0)                                                              \
    do {                                                                        \
        float4 z = make_float4(0.f, 0.f, 0.f, 0.f);                             \
        vx[0] = (xt0 >= 0) ? *(const float4*)(xp0 + (K0) + xfq * 4) : z;        \
        vx[1] = (xt0 >= 0) ? *(const float4*)(xp0 + (K0) + 32 + xfq * 4) : z;   \
        vx[2] = (xt1 >= 0) ? *(const float4*)(xp1 + (K0) + xfq * 4) : z;        \
        vx[3] = (xt1 >= 0) ? *(const float4*)(xp1 + (K0) + 32 + xfq * 4) : z;   \
    } while (0)

#define STORE_X(BUF)                                                            \
    do {                                                                        \
        char* xb_ = smc + SM_X0 + (BUF) * X_STRIDE;                             \
        *(float4*)(xb_ + xfr * X_ROWB + xfq * 16)              = vx[0];         \
        *(float4*)(xb_ + xfr * X_ROWB + 128 + xfq * 16)        = vx[1];         \
        *(float4*)(xb_ + (xfr + 64) * X_ROWB + xfq * 16)       = vx[2];         \
        *(float4*)(xb_ + (xfr + 64) * X_ROWB + 128 + xfq * 16) = vx[3];         \
    } while (0)

#define LOAD_A(K0)                                                              \
    do {                                                                        \
        _Pragma("unroll") for (int i = 0; i < 2; ++i) va[i] =                   \
            *(const float4*)(Arow + (size_t)fr * DIM + (K0) + fq * 4 + i * 32); \
    } while (0)

#define STORE_A(BUF)                                                            \
    do {                                                                        \
        char* ah = smc + SM_A0 + (BUF) * A_STRIDE;                              \
        char* al = ah + 8192;                                                   \
        _Pragma("unroll") for (int i = 0; i < 2; ++i) {                         \
            uint32_t h0, l0, h1, l1;                                            \
            split2(va[i].x, va[i].y, h0, l0);                                   \
            split2(va[i].z, va[i].w, h1, l1);                                   \
            uint32_t off = swz((uint32_t)fr * 128 + fq * 8 + i * 64);           \
            *(uint2*)(ah + off) = make_uint2(h0, h1);                           \
            *(uint2*)(al + off) = make_uint2(l0, l1);                           \
        }                                                                       \
    } while (0)

    // ===== stage 1: H[128,64] = X[128,2048] * A_e^T =====
    float acc1[4][4];
#pragma unroll
    for (int j = 0; j < 4; ++j)
#pragma unroll
        for (int q = 0; q < 4; ++q) acc1[j][q] = 0.f;

    LOAD_X(0);
    LOAD_A(0);
    STORE_X(0);
    STORE_A(0);
    __syncthreads();
    LOAD_X(64);
    LOAD_A(64);

    // fragment-read offsets within X SMEM tile
    const uint32_t xo0 = (uint32_t)(s1mg * 16 + g) * X_ROWB + tq * 8;
    const uint32_t xo1 = (uint32_t)(s1mg * 16 + 8 + g) * X_ROWB + tq * 8;

    for (int c = 0; c < 32; ++c) {
        const char* xb = smc + SM_X0 + (c & 1) * X_STRIDE;
        const uint32_t ahB = sbu + SM_A0 + (uint32_t)(c & 1) * A_STRIDE;
#pragma unroll
        for (int kk = 0; kk < 4; ++kk) {
            float2 rw0 = *(const float2*)(xb + xo0 + kk * 64);
            float2 rw1 = *(const float2*)(xb + xo1 + kk * 64);
            float2 rw2 = *(const float2*)(xb + xo0 + kk * 64 + 32);
            float2 rw3 = *(const float2*)(xb + xo1 + kk * 64 + 32);
            uint32_t xh[4], xl[4];
            split2(rw0.x, rw0.y, xh[0], xl[0]);
            split2(rw1.x, rw1.y, xh[1], xl[1]);
            split2(rw2.x, rw2.y, xh[2], xl[2]);
            split2(rw3.x, rw3.y, xh[3], xl[3]);
#pragma unroll
            for (int jj = 0; jj < 2; ++jj) {
                uint32_t bh[4], bl[4];
                uint32_t ao = swz((uint32_t)(s1ng * 32 + jj * 16) * 128 + bpair + kk * 32);
                ldm_x4(ahB + ao, bh);
                ldm_x4(ahB + 8192 + ao, bl);
                mma16816(acc1[jj * 2], xh, bh);
                mma16816(acc1[jj * 2], xh, bl);
                mma16816(acc1[jj * 2], xl, bh);
                mma16816(acc1[jj * 2 + 1], xh, bh + 2);
                mma16816(acc1[jj * 2 + 1], xh, bl + 2);
                mma16816(acc1[jj * 2 + 1], xl, bh + 2);
            }
        }
        if (c < 31) {
            STORE_X((c + 1) & 1);
            STORE_A((c + 1) & 1);
            if (c < 30) {
                LOAD_X((c + 2) * 64);
                LOAD_A((c + 2) * 64);
            }
        }
        __syncthreads();
    }

    // ===== stage 2 fills (B): 128n x 64r fp32 per chunk =====
    // thread handles rows {bfn, bfn+64}, per row two float4 at r = bfq*4 (+32)
    const int bfn = tid >> 3, bfq = tid & 7;
    float4 vb[4];

#define LOAD_B(N0)                                                              \
    do {                                                                        \
        const float* s0 = Brow + (size_t)((N0) + bfn) * RNK + bfq * 4;          \
        const float* s1 = Brow + (size_t)((N0) + bfn + 64) * RNK + bfq * 4;     \
        vb[0] = *(const float4*)(s0);                                           \
        vb[1] = *(const float4*)(s0 + 32);                                      \
        vb[2] = *(const float4*)(s1);                                           \
        vb[3] = *(const float4*)(s1 + 32);                                      \
    } while (0)

#define STORE_B(BUF)                                                            \
    do {                                                                        \
        char* bh_ = smc + SM_B0 + (BUF) * B_STRIDE;                             \
        char* bl_ = bh_ + 16384;                                                \
        _Pragma("unroll") for (int i = 0; i < 4; ++i) {                         \
            uint32_t h0, l0, h1, l1;                                            \
            split2(vb[i].x, vb[i].y, h0, l0);                                   \
            split2(vb[i].z, vb[i].w, h1, l1);                                   \
            uint32_t row = (uint32_t)bfn + (i >> 1) * 64;                       \
            uint32_t off = swz(row * 128 + bfq * 8 + (i & 1) * 64);             \
            *(uint2*)(bh_ + off) = make_uint2(h0, h1);                          \
            *(uint2*)(bl_ + off) = make_uint2(l0, l1);                          \
        }                                                                       \
    } while (0)

    LOAD_B(0);   // start GMEM reads early

    // ===== H -> SMEM bf16 hi/lo (fragment-consistent layout) =====
    {
        char* hh = smc + SM_HHI;
        char* hl = smc + SM_HLO;
#pragma unroll
        for (int j = 0; j < 4; ++j) {
            int col = s1ng * 32 + j * 8 + 2 * tq;
            int r0 = s1mg * 16 + g;
            uint32_t hi, lo;
            split2(acc1[j][0], acc1[j][1], hi, lo);
            uint32_t off = swz((uint32_t)r0 * 128 + (uint32_t)col * 2);
            *(uint32_t*)(hh + off) = hi;
            *(uint32_t*)(hl + off) = lo;
            split2(acc1[j][2], acc1[j][3], hi, lo);
            uint32_t off2 = swz((uint32_t)(r0 + 8) * 128 + (uint32_t)col * 2);
            *(uint32_t*)(hh + off2) = hi;
            *(uint32_t*)(hl + off2) = lo;
        }
    }
    STORE_B(0);
    __syncthreads();

    // preload ALL H fragments into registers (reused across all 16 n-chunks)
    uint32_t hfh[2][4][4], hfl[2][4][4];
#pragma unroll
    for (int mt = 0; mt < 2; ++mt)
#pragma unroll
        for (int kk = 0; kk < 4; ++kk) {
            uint32_t ho = swz((uint32_t)(s2mg * 32 + mt * 16) * 128 + apat + kk * 32);
            ldm_x4(sbu + SM_HHI + ho, hfh[mt][kk]);
            ldm_x4(sbu + SM_HLO + ho, hfl[mt][kk]);
        }

    // stage-2 output tokens for this warp
    int tko[2][2];
#pragma unroll
    for (int mt = 0; mt < 2; ++mt) {
        tko[mt][0] = tok[s2mg * 32 + mt * 16 + g];
        tko[mt][1] = tok[s2mg * 32 + mt * 16 + 8 + g];
    }

    LOAD_B(128);

    // ===== stage 2: O[128,2048] = H[128,64] * B_e^T, 16 n-chunks of 128 =====
    for (int nc = 0; nc < 16; ++nc) {
        float acc2[2][4][4];
#pragma unroll
        for (int mt = 0; mt < 2; ++mt)
#pragma unroll
            for (int j = 0; j < 4; ++j)
#pragma unroll
                for (int q = 0; q < 4; ++q) acc2[mt][j][q] = 0.f;

        const uint32_t bbB = sbu + SM_B0 + (uint32_t)(nc & 1) * B_STRIDE;
#pragma unroll
        for (int kk = 0; kk < 4; ++kk) {
#pragma unroll
            for (int jj = 0; jj < 2; ++jj) {
                uint32_t bh[4], bl[4];
                uint32_t bo = swz((uint32_t)(s2ng * 32 + jj * 16) * 128 + bpair + kk * 32);
                ldm_x4(bbB + bo, bh);
                ldm_x4(bbB + 16384 + bo, bl);
#pragma unroll
                for (int mt = 0; mt < 2; ++mt) {
                    mma16816(acc2[mt][jj * 2], hfh[mt][kk], bh);
                    mma16816(acc2[mt][jj * 2], hfh[mt][kk], bl);
                    mma16816(acc2[mt][jj * 2], hfl[mt][kk], bh);
                    mma16816(acc2[mt][jj * 2 + 1], hfh[mt][kk], bh + 2);
                    mma16816(acc2[mt][jj * 2 + 1], hfh[mt][kk], bl + 2);
                    mma16816(acc2[mt][jj * 2 + 1], hfl[mt][kk], bh + 2);
                }
            }
        }

        // epilogue: direct STG.64
        const int nb0 = nc * 128 + s2ng * 32 + 2 * tq;
#pragma unroll
        for (int mt = 0; mt < 2; ++mt)
#pragma unroll
            for (int j = 0; j < 4; ++j) {
                int colo = nb0 + j * 8;
                if (tko[mt][0] >= 0)
                    *(float2*)(out + (size_t)tko[mt][0] * DIM + colo) =
                        make_float2(acc2[mt][j][0], acc2[mt][j][1]);
                if (tko[mt][1] >= 0)
                    *(float2*)(out + (size_t)tko[mt][1] * DIM + colo) =
                        make_float2(acc2[mt][j][2], acc2[mt][j][3]);
            }

        if (nc < 15) {
            STORE_B((nc + 1) & 1);
            if (nc < 14) LOAD_B((nc + 2) * 128);
        }
        __syncthreads();
    }
}

// ---------------- launch ----------------
extern "C" void kernel_launch(void* const* d_in, const int* in_sizes, int n_in,
                              void* d_out, int out_size) {
    const float* x  = (const float*)d_in[0];   // [B,S,D]
    const float* Aw = (const float*)d_in[1];   // [E,R,D]
    const float* Bw = (const float*)d_in[2];   // [E,D,R]
    const int*   ti = (const int*)d_in[3];     // [B,S]
    float* out = (float*)d_out;
    (void)in_sizes; (void)n_in; (void)out_size;

    static int smem_set = 0;
    if (!smem_set) {
        cudaFuncSetAttribute(k_main, cudaFuncAttributeMaxDynamicSharedMemorySize, SMEM_BYTES);
        smem_set = 1;
    }

    k_sort<<<1, 1024>>>(ti);
    dim3 grid(NTOK / TM, E_N, 1);
    k_main<<<grid, NTHR, SMEM_BYTES>>>(x, Aw, Bw, out);
}